// round 5
// baseline (speedup 1.0000x reference)
#include <cuda_runtime.h>
#include <math.h>
#include <stdint.h>

#define OBS   128
#define PROJ  64
#define HID   256
#define LAT   24
#define BB    1024
#define TT    256
#define G3    768
#define NCTA  148
#define CHR   16      // rows per chunk in sweep

// ---- device scratch --------------------------------------------------------
__device__ float  g_gx [(size_t)BB * TT * G3];   // input-side gates [B*T,768]
__device__ float  g_seq[(size_t)BB * TT * HID];  // h per (b,t)      [B*T,256]
__device__ float4 g_Wt4[(HID / 4) * G3];         // W_hh [k4][col] float4(4 k's)
__device__ unsigned char g_d[BB * TT];           // chain depth per item
__device__ int g_hist[256];
__device__ int g_boff[257];
__device__ int g_cur[256];
__device__ int g_items[BB * TT];
__device__ int g_maxd;
__device__ int g_barcnt;

// ---- helpers ---------------------------------------------------------------
__device__ __forceinline__ void fma2(float2& d, float2 a, float2 b) {
    unsigned long long& dd = reinterpret_cast<unsigned long long&>(d);
    asm("fma.rn.f32x2 %0, %1, %2, %0;"
        : "+l"(dd)
        : "l"(reinterpret_cast<const unsigned long long&>(a)),
          "l"(reinterpret_cast<const unsigned long long&>(b)));
}
__device__ __forceinline__ float tanha(float x) {
    float y; asm("tanh.approx.f32 %0, %1;" : "=f"(y) : "f"(x)); return y;
}
__device__ __forceinline__ float siga(float x) {
    return fmaf(0.5f, tanha(0.5f * x), 0.5f);
}

// ---- zero: reset all per-run mutable scratch -------------------------------
__global__ void zero_kernel() {
    int t = threadIdx.x;
    g_hist[t] = 0;
    g_cur[t] = 0;
    if (t == 0) { g_barcnt = 0; g_maxd = 0; }
}

// ---- tr: W_hh repack -------------------------------------------------------
__global__ void tr_kernel(const float* __restrict__ W) {
    int idx = blockIdx.x * 256 + threadIdx.x;
    if (idx >= (HID / 4) * G3) return;
    int k4 = idx / G3, col = idx - k4 * G3;
    float4 v;
    v.x = W[(size_t)(4 * k4 + 0) * G3 + col];
    v.y = W[(size_t)(4 * k4 + 1) * G3 + col];
    v.z = W[(size_t)(4 * k4 + 2) * G3 + col];
    v.w = W[(size_t)(4 * k4 + 3) * G3 + col];
    g_Wt4[idx] = v;
}

// ---- prep_d: per-row walk computing chain depth + histogram ---------------
__global__ void prepd_kernel(const int* __restrict__ is_init) {
    int b = blockIdx.x * 256 + threadIdx.x;   // grid 4 x 256 = 1024
    const int* ii = is_init + (size_t)b * TT;
    int cnt[8] = {0, 0, 0, 0, 0, 0, 0, 0};
    int d = 0;
    for (int t = 0; t < TT; t++) {
        bool m = (ii[t] != 0);
        d = (m || t == 0) ? 0 : d + 1;
        g_d[b * TT + t] = (unsigned char)d;
        if (d < 8) cnt[d]++;
        else atomicAdd(&g_hist[d], 1);
    }
    #pragma unroll
    for (int j = 0; j < 8; j++)
        if (cnt[j]) atomicAdd(&g_hist[j], cnt[j]);
}

// ---- scan: bucket offsets + max depth --------------------------------------
__global__ void scan_kernel() {
    if (threadIdx.x == 0) {
        int acc = 0, mx = 0;
        for (int k = 0; k < 256; k++) {
            g_boff[k] = acc;
            acc += g_hist[k];
            if (g_hist[k] > 0) mx = k;
        }
        g_boff[256] = acc;
        g_maxd = mx;
    }
}

// ---- scatter: items into buckets (two-level atomics) -----------------------
__global__ void scatter_kernel() {
    __shared__ int s_cnt[256], s_base[256], s_off[256];
    int tid = threadIdx.x;
    s_cnt[tid] = 0; s_off[tid] = 0;
    __syncthreads();
    int d4[4], i4[4];
    #pragma unroll
    for (int j = 0; j < 4; j++) {
        int i = blockIdx.x * 1024 + j * 256 + tid;
        i4[j] = i; d4[j] = g_d[i];
        atomicAdd(&s_cnt[d4[j]], 1);
    }
    __syncthreads();
    if (s_cnt[tid]) s_base[tid] = atomicAdd(&g_cur[tid], s_cnt[tid]);
    __syncthreads();
    #pragma unroll
    for (int j = 0; j < 4; j++) {
        int lo = atomicAdd(&s_off[d4[j]], 1);
        g_items[g_boff[d4[j]] + s_base[d4[j]] + lo] = i4[j];
    }
}

// ---- pre: gx = (obs@W_in + b_in)@W_ih + b_ih (unchanged from R3) -----------
__global__ __launch_bounds__(256) void pre_kernel(
    const float* __restrict__ obs, const float* __restrict__ W_in,
    const float* __restrict__ b_in, const float* __restrict__ W_ih,
    const float* __restrict__ b_ih)
{
    __shared__ float s_obsT[OBS][34];
    __shared__ float s_x2[PROJ][34];

    const int tid = threadIdx.x;
    const size_t row0 = (size_t)blockIdx.x * 32;

    for (int i = tid; i < 32 * OBS; i += 256) {
        int r = i >> 7, k = i & 127;
        s_obsT[k][r] = obs[(row0 + r) * OBS + k];
    }
    __syncthreads();

    {
        const int p = tid & 63, rh = tid >> 6;
        const float bi = b_in[p];
        float2 acc[4];
        #pragma unroll
        for (int pr = 0; pr < 4; pr++) acc[pr] = make_float2(bi, bi);
        #pragma unroll 4
        for (int k = 0; k < OBS; k++) {
            float w = W_in[k * PROJ + p];
            float2 w2 = make_float2(w, w);
            #pragma unroll
            for (int pr = 0; pr < 4; pr++)
                fma2(acc[pr], w2, *(const float2*)&s_obsT[k][8 * rh + 2 * pr]);
        }
        #pragma unroll
        for (int pr = 0; pr < 4; pr++) {
            s_x2[p][8 * rh + 2 * pr]     = acc[pr].x;
            s_x2[p][8 * rh + 2 * pr + 1] = acc[pr].y;
        }
    }
    __syncthreads();

    const int j = tid;
    const float bh0 = b_ih[j], bh1 = b_ih[j + 256], bh2 = b_ih[j + 512];
    for (int rt = 0; rt < 2; rt++) {
        float2 a0[8], a1[8], a2[8];
        #pragma unroll
        for (int pr = 0; pr < 8; pr++) {
            a0[pr] = make_float2(bh0, bh0);
            a1[pr] = make_float2(bh1, bh1);
            a2[pr] = make_float2(bh2, bh2);
        }
        #pragma unroll 2
        for (int p = 0; p < PROJ; p++) {
            float w0 = W_ih[p * G3 + j];
            float w1 = W_ih[p * G3 + j + 256];
            float w2 = W_ih[p * G3 + j + 512];
            float2 w02 = make_float2(w0, w0);
            float2 w12 = make_float2(w1, w1);
            float2 w22 = make_float2(w2, w2);
            #pragma unroll
            for (int pr = 0; pr < 8; pr++) {
                float2 xv = *(const float2*)&s_x2[p][16 * rt + 2 * pr];
                fma2(a0[pr], w02, xv);
                fma2(a1[pr], w12, xv);
                fma2(a2[pr], w22, xv);
            }
        }
        #pragma unroll
        for (int pr = 0; pr < 8; pr++) {
            size_t r = row0 + rt * 16 + 2 * pr;
            g_gx[r * G3 + j]             = a0[pr].x;
            g_gx[(r + 1) * G3 + j]       = a0[pr].y;
            g_gx[r * G3 + j + 256]       = a1[pr].x;
            g_gx[(r + 1) * G3 + j + 256] = a1[pr].y;
            g_gx[r * G3 + j + 512]       = a2[pr].x;
            g_gx[(r + 1) * G3 + j + 512] = a2[pr].y;
        }
    }
}

// ---- sweep: bucketed parallel GRU steps ------------------------------------
// 148 persistent CTAs x 256 threads. q = blockIdx.x & 3 -> hidden units
// q*64..q*64+63 (weight quarter cached in SMEM, 192 KB). Worker w = bid>>2
// (0..36) takes chunks c = w, w+37, ... of CHR=16 rows per bucket.
// Thread: u = tid&63 (unit), rg = tid>>6 -> rows rg*4..rg*4+3.
// FFMA2 pairs along k (aligned halves of float4 -> no packing movs).
static const int SW_BYTES = 64 * 192 * 16 + CHR * HID * 4 + 2 * CHR * 4 + 128;

__global__ __launch_bounds__(256) void sweep_kernel(
    const int* __restrict__ is_init, const float* __restrict__ hx,
    const float* __restrict__ b_hh)
{
    extern __shared__ char sm[];
    float4* s_w   = (float4*)sm;                       // [64 k4][192 slots]
    float*  s_h   = (float*)(sm + 64 * 192 * 16);      // [CHR][HID]
    int*    s_it  = (int*)(sm + 64 * 192 * 16 + CHR * HID * 4);
    int*    s_fl  = s_it + CHR;

    const int tid = threadIdx.x;
    const int q   = blockIdx.x & 3;
    const int wkr = blockIdx.x >> 2;                   // 0..36
    const int u   = tid & 63;
    const int rg  = tid >> 6;
    const int gu  = q * 64 + u;

    // cache weight quarter: slot = gate*64 + u -> col = gate*256 + gu
    for (int i = tid; i < 64 * 192; i += 256) {
        int k4 = i / 192, slot = i - k4 * 192;
        int gate = slot >> 6, uu = slot & 63;
        s_w[i] = g_Wt4[(size_t)k4 * G3 + gate * 256 + q * 64 + uu];
    }
    const float bhr = b_hh[gu], bhz = b_hh[256 + gu], bhn = b_hh[512 + gu];
    __syncthreads();

    const int maxd = g_maxd;
    int ep = 0;

    for (int k = 0; k <= maxd; k++) {
        const int base = g_boff[k];
        const int cnt  = g_boff[k + 1] - base;
        const int nch  = (cnt + CHR - 1) / CHR;

        for (int c = wkr; c < nch; c += 37) {
            // ---- stage row metadata ----
            if (tid < CHR) {
                int pos = base + c * CHR + tid;
                int it = -1, fl = 1;
                if (pos < base + cnt) {
                    it = g_items[pos];
                    if (k == 0) {
                        int b = it >> 8, t = it & 255;
                        fl = (is_init[(size_t)b * TT + t] != 0) ? 1 : 2;  // 1=zero 2=hx
                    } else fl = 0;                                         // 0=g_seq[t-1]
                }
                s_it[tid] = it; s_fl[tid] = fl;
            }
            __syncthreads();
            // ---- stage h_prev: [row][k] coalesced ----
            for (int i = tid; i < CHR * 64; i += 256) {
                int row = i >> 6, seg = i & 63;
                int it = s_it[row], fl = s_fl[row];
                float4 v = make_float4(0.f, 0.f, 0.f, 0.f);
                if (it >= 0) {
                    if (fl == 0)
                        v = *(const float4*)&g_seq[(size_t)(it - 1) * HID + seg * 4];
                    else if (fl == 2)
                        v = *(const float4*)&hx[(size_t)(it >> 8) * HID + seg * 4];
                }
                *(float4*)&s_h[row * HID + seg * 4] = v;
            }
            __syncthreads();

            // ---- gx prefetch for this thread's 4 rows ----
            const int row0 = rg * 4;
            float gxr[4], gxz[4], gxn[4];
            int itl[4];
            #pragma unroll
            for (int r = 0; r < 4; r++) {
                int it = s_it[row0 + r];
                itl[r] = it;
                if (it >= 0) {
                    const float* g = g_gx + (size_t)it * G3 + gu;
                    gxr[r] = g[0]; gxz[r] = g[256]; gxn[r] = g[512];
                } else { gxr[r] = gxz[r] = gxn[r] = 0.f; }
            }

            // ---- GEMV, FFMA2 along k ----
            float2 aR[4], aZ[4], aN[4];
            #pragma unroll
            for (int r = 0; r < 4; r++) {
                aR[r] = make_float2(0.f, 0.f);
                aZ[r] = make_float2(0.f, 0.f);
                aN[r] = make_float2(0.f, 0.f);
            }
            #pragma unroll 8
            for (int k4 = 0; k4 < 64; k4++) {
                float4 wr = s_w[k4 * 192 + u];
                float4 wz = s_w[k4 * 192 + 64 + u];
                float4 wn = s_w[k4 * 192 + 128 + u];
                float2 wr0 = make_float2(wr.x, wr.y), wr1 = make_float2(wr.z, wr.w);
                float2 wz0 = make_float2(wz.x, wz.y), wz1 = make_float2(wz.z, wz.w);
                float2 wn0 = make_float2(wn.x, wn.y), wn1 = make_float2(wn.z, wn.w);
                #pragma unroll
                for (int r = 0; r < 4; r++) {
                    float4 hv = *(const float4*)&s_h[(row0 + r) * HID + 4 * k4];
                    float2 h0 = make_float2(hv.x, hv.y);
                    float2 h1 = make_float2(hv.z, hv.w);
                    fma2(aR[r], wr0, h0); fma2(aR[r], wr1, h1);
                    fma2(aZ[r], wz0, h0); fma2(aZ[r], wz1, h1);
                    fma2(aN[r], wn0, h0); fma2(aN[r], wn1, h1);
                }
            }

            // ---- gates + store ----
            #pragma unroll
            for (int r = 0; r < 4; r++) {
                if (itl[r] < 0) continue;
                float hp = s_h[(row0 + r) * HID + gu];
                float rr = siga(gxr[r] + aR[r].x + aR[r].y + bhr);
                float zz = siga(gxz[r] + aZ[r].x + aZ[r].y + bhz);
                float nn = tanha(gxn[r] + rr * (aN[r].x + aN[r].y + bhn));
                float hn = nn + zz * (hp - nn);
                g_seq[(size_t)itl[r] * HID + gu] = hn;
            }
            __syncthreads();   // s_h reuse
        }

        // ---- grid barrier (monotonic counter, all 148 CTAs resident) ----
        if (k < maxd) {
            __syncthreads();
            if (tid == 0) {
                __threadfence();
                atomicAdd(&g_barcnt, 1);
                int target = (++ep) * NCTA;
                while (*(volatile int*)&g_barcnt < target) __nanosleep(32);
            }
            __syncthreads();
        }
    }
}

// ---- post: out = mish(seq) @ W_out + b_out (unchanged from R3) -------------
__global__ __launch_bounds__(256) void post_kernel(
    const float* __restrict__ W_out, const float* __restrict__ b_out,
    float* __restrict__ out)
{
    __shared__ float s_m2[HID][32];

    const int tid = threadIdx.x;
    const size_t row0 = (size_t)blockIdx.x * 32;

    {
        const int row = tid & 31;
        const int kc  = (tid >> 5) * 32;
        const float* src = g_seq + (row0 + row) * HID + kc;
        #pragma unroll
        for (int c = 0; c < 8; c++) {
            float4 v = *(const float4*)(src + 4 * c);
            float hv[4] = {v.x, v.y, v.z, v.w};
            #pragma unroll
            for (int e = 0; e < 4; e++) {
                float h = hv[e];
                float sp = __logf(1.f + __expf(h));
                s_m2[kc + 4 * c + e][row] = h * tanha(sp);
            }
        }
    }
    __syncthreads();

    if (tid < 192) {
        const int pg = tid / 24;
        const int l  = tid - pg * 24;
        float2 a0 = make_float2(0.f, 0.f), a1 = make_float2(0.f, 0.f);
        #pragma unroll 4
        for (int k = 0; k < HID; k++) {
            float4 m4 = *(const float4*)&s_m2[k][4 * pg];
            float w = __ldg(W_out + k * LAT + l);
            float2 w2 = make_float2(w, w);
            fma2(a0, w2, make_float2(m4.x, m4.y));
            fma2(a1, w2, make_float2(m4.z, m4.w));
        }
        const float bl = b_out[l];
        out[(row0 + 4 * pg + 0) * LAT + l] = a0.x + bl;
        out[(row0 + 4 * pg + 1) * LAT + l] = a0.y + bl;
        out[(row0 + 4 * pg + 2) * LAT + l] = a1.x + bl;
        out[(row0 + 4 * pg + 3) * LAT + l] = a1.y + bl;
    }
}

// ---- hfin: h_final = h(T-1) -------------------------------------------------
__global__ void hfin_kernel(float* __restrict__ hf) {
    int i = blockIdx.x * 256 + threadIdx.x;     // BB*HID
    int b = i >> 8, k = i & 255;
    hf[i] = g_seq[((size_t)b * TT + TT - 1) * HID + k];
}

// ---------------------------------------------------------------------------
extern "C" void kernel_launch(void* const* d_in, const int* in_sizes, int n_in,
                              void* d_out, int out_size) {
    const float* obs     = (const float*)d_in[0];
    const int*   is_init = (const int*)  d_in[1];
    const float* hx      = (const float*)d_in[2];
    const float* W_in    = (const float*)d_in[3];
    const float* b_in    = (const float*)d_in[4];
    const float* W_ih    = (const float*)d_in[5];
    const float* b_ih    = (const float*)d_in[6];
    const float* W_hh    = (const float*)d_in[7];
    const float* b_hh    = (const float*)d_in[8];
    const float* W_out   = (const float*)d_in[9];
    const float* b_out   = (const float*)d_in[10];

    float* out     = (float*)d_out;                 // [B,T,LAT]
    float* h_final = out + (size_t)BB * TT * LAT;   // [B,HID]

    cudaFuncSetAttribute(sweep_kernel,
                         cudaFuncAttributeMaxDynamicSharedMemorySize, SW_BYTES);

    zero_kernel<<<1, 256>>>();
    tr_kernel<<<((HID / 4) * G3 + 255) / 256, 256>>>(W_hh);
    prepd_kernel<<<4, 256>>>(is_init);
    scan_kernel<<<1, 32>>>();
    scatter_kernel<<<BB * TT / 1024, 256>>>();
    pre_kernel<<<(BB * TT) / 32, 256>>>(obs, W_in, b_in, W_ih, b_ih);
    sweep_kernel<<<NCTA, 256, SW_BYTES>>>(is_init, hx, b_hh);
    post_kernel<<<(BB * TT) / 32, 256>>>(W_out, b_out, out);
    hfin_kernel<<<BB * HID / 256, 256>>>(h_final);
}

// round 6
// speedup vs baseline: 1.0805x; 1.0805x over previous
#include <cuda_runtime.h>
#include <math.h>
#include <stdint.h>

#define OBS   128
#define PROJ  64
#define HID   256
#define LAT   24
#define BB    1024
#define TT    256
#define G3    768

// ---- device scratch --------------------------------------------------------
__device__ float    g_gx [(size_t)BB * TT * G3];   // input-side gates
__device__ float    g_seq[(size_t)BB * TT * HID];  // h per (b,t)
__device__ float4   g_Wt4[(HID / 4) * G3];         // W_hh [k4][col], 4 k's packed
__device__ uint32_t g_mb [BB * 8];                 // is_init bit-packed per row

// ---- helpers ---------------------------------------------------------------
__device__ __forceinline__ void fma2(float2& d, float2 a, float2 b) {
    unsigned long long& dd = reinterpret_cast<unsigned long long&>(d);
    asm("fma.rn.f32x2 %0, %1, %2, %0;"
        : "+l"(dd)
        : "l"(reinterpret_cast<const unsigned long long&>(a)),
          "l"(reinterpret_cast<const unsigned long long&>(b)));
}
__device__ __forceinline__ float tanha(float x) {
    float y; asm("tanh.approx.f32 %0, %1;" : "=f"(y) : "f"(x)); return y;
}
__device__ __forceinline__ float siga(float x) {
    return fmaf(0.5f, tanha(0.5f * x), 0.5f);
}

// ---- tr: W_hh repack -------------------------------------------------------
__global__ void tr_kernel(const float* __restrict__ W) {
    int idx = blockIdx.x * 256 + threadIdx.x;
    if (idx >= (HID / 4) * G3) return;
    int k4 = idx / G3, col = idx - k4 * G3;
    float4 v;
    v.x = W[(size_t)(4 * k4 + 0) * G3 + col];
    v.y = W[(size_t)(4 * k4 + 1) * G3 + col];
    v.z = W[(size_t)(4 * k4 + 2) * G3 + col];
    v.w = W[(size_t)(4 * k4 + 3) * G3 + col];
    g_Wt4[idx] = v;
}

// ---- mask: bit-pack is_init ------------------------------------------------
__global__ void mask_kernel(const int* __restrict__ is_init) {
    int i = blockIdx.x * 256 + threadIdx.x;     // 8192 = BB*8
    int b = i >> 3, w = i & 7;
    const int* p = is_init + (size_t)b * TT + w * 32;
    uint32_t m = 0;
    #pragma unroll 8
    for (int j = 0; j < 32; j++) m |= (p[j] != 0 ? 1u : 0u) << j;
    g_mb[i] = m;
}

// ---- pre: gx = (obs@W_in + b_in)@W_ih + b_ih (unchanged, proven) -----------
__global__ __launch_bounds__(256) void pre_kernel(
    const float* __restrict__ obs, const float* __restrict__ W_in,
    const float* __restrict__ b_in, const float* __restrict__ W_ih,
    const float* __restrict__ b_ih)
{
    __shared__ float s_obsT[OBS][34];
    __shared__ float s_x2[PROJ][34];

    const int tid = threadIdx.x;
    const size_t row0 = (size_t)blockIdx.x * 32;

    for (int i = tid; i < 32 * OBS; i += 256) {
        int r = i >> 7, k = i & 127;
        s_obsT[k][r] = obs[(row0 + r) * OBS + k];
    }
    __syncthreads();

    {
        const int p = tid & 63, rh = tid >> 6;
        const float bi = b_in[p];
        float2 acc[4];
        #pragma unroll
        for (int pr = 0; pr < 4; pr++) acc[pr] = make_float2(bi, bi);
        #pragma unroll 4
        for (int k = 0; k < OBS; k++) {
            float w = W_in[k * PROJ + p];
            float2 w2 = make_float2(w, w);
            #pragma unroll
            for (int pr = 0; pr < 4; pr++)
                fma2(acc[pr], w2, *(const float2*)&s_obsT[k][8 * rh + 2 * pr]);
        }
        #pragma unroll
        for (int pr = 0; pr < 4; pr++) {
            s_x2[p][8 * rh + 2 * pr]     = acc[pr].x;
            s_x2[p][8 * rh + 2 * pr + 1] = acc[pr].y;
        }
    }
    __syncthreads();

    const int j = tid;
    const float bh0 = b_ih[j], bh1 = b_ih[j + 256], bh2 = b_ih[j + 512];
    for (int rt = 0; rt < 2; rt++) {
        float2 a0[8], a1[8], a2[8];
        #pragma unroll
        for (int pr = 0; pr < 8; pr++) {
            a0[pr] = make_float2(bh0, bh0);
            a1[pr] = make_float2(bh1, bh1);
            a2[pr] = make_float2(bh2, bh2);
        }
        #pragma unroll 2
        for (int p = 0; p < PROJ; p++) {
            float w0 = W_ih[p * G3 + j];
            float w1 = W_ih[p * G3 + j + 256];
            float w2 = W_ih[p * G3 + j + 512];
            float2 w02 = make_float2(w0, w0);
            float2 w12 = make_float2(w1, w1);
            float2 w22 = make_float2(w2, w2);
            #pragma unroll
            for (int pr = 0; pr < 8; pr++) {
                float2 xv = *(const float2*)&s_x2[p][16 * rt + 2 * pr];
                fma2(a0[pr], w02, xv);
                fma2(a1[pr], w12, xv);
                fma2(a2[pr], w22, xv);
            }
        }
        #pragma unroll
        for (int pr = 0; pr < 8; pr++) {
            size_t r = row0 + rt * 16 + 2 * pr;
            g_gx[r * G3 + j]             = a0[pr].x;
            g_gx[(r + 1) * G3 + j]       = a0[pr].y;
            g_gx[r * G3 + j + 256]       = a1[pr].x;
            g_gx[(r + 1) * G3 + j + 256] = a1[pr].y;
            g_gx[r * G3 + j + 512]       = a2[pr].x;
            g_gx[(r + 1) * G3 + j + 512] = a2[pr].y;
        }
    }
}

// ---- rec: cluster-4 scan, weight quarter resident in SMEM ------------------
// 32 clusters x 4 CTAs = 128 CTAs x 256 threads. Cluster c: rows 32c..32c+31.
// CTA rank q: hidden units q*64..q*64+63; weight quarter (192 KB) in SMEM.
// Thread: rg = tid&3 (rows rg*8..rg*8+7 = pairs rg*4..rg*4+3), u = tid>>2.
// h single-buffered in SMEM pair-packed s_h2[k][pair]; two cluster barriers
// per step (read-done, write-visible); h slice DSMEM'd to 3 peers.
#define REC_SMEM (64 * 3 * 64 * 16 + HID * 16 * 8)   // 192KB + 32KB

__global__ __launch_bounds__(256) __cluster_dims__(4, 1, 1)
void rec_kernel(const float* __restrict__ hx, const float* __restrict__ b_hh,
                float* __restrict__ h_final)
{
    extern __shared__ char sm[];
    float4* s_w  = (float4*)sm;                      // [(k4*3+gate)*64+u]
    float2* s_h2 = (float2*)(sm + 64 * 3 * 64 * 16); // [k][pair], 16 pairs

    const int tid = threadIdx.x;
    const int q   = blockIdx.x & 3;
    const int b0  = (blockIdx.x >> 2) * 32;
    const int rg  = tid & 3;
    const int u   = tid >> 2;
    const int gu  = q * 64 + u;
    const int p0  = rg * 4;
    const int r0  = rg * 8;

    // cache weight quarter
    for (int i = tid; i < 64 * 3 * 64; i += 256) {
        int k4 = i / 192, rem = i - k4 * 192;
        int g = rem >> 6, uu = rem & 63;
        s_w[i] = g_Wt4[(size_t)k4 * G3 + g * 256 + q * 64 + uu];
    }
    // init h: hx masked by bit 0
    for (int i = tid; i < HID * 16; i += 256) {
        int k = i >> 4, p = i & 15;
        float h0 = (g_mb[(b0 + 2 * p) * 8] & 1u)     ? 0.f : hx[(size_t)(b0 + 2 * p) * HID + k];
        float h1 = (g_mb[(b0 + 2 * p + 1) * 8] & 1u) ? 0.f : hx[(size_t)(b0 + 2 * p + 1) * HID + k];
        s_h2[k * 16 + p] = make_float2(h0, h1);
    }
    const float bhr = b_hh[gu], bhz = b_hh[256 + gu], bhn = b_hh[512 + gu];

    // mask words for window 0, this thread's 8 rows
    uint32_t mw[8];
    #pragma unroll
    for (int r = 0; r < 8; r++) mw[r] = g_mb[(b0 + r0 + r) * 8];

    // peer s_h2 bases (3 peers)
    uint32_t my_h;
    asm("{ .reg .u64 t0; cvta.to.shared.u64 t0, %1; cvt.u32.u64 %0, t0; }"
        : "=r"(my_h) : "l"(s_h2));
    uint32_t peer_h[3];
    #pragma unroll
    for (int e = 0; e < 3; e++) {
        int pr = (q + 1 + e) & 3;
        asm("mapa.shared::cluster.u32 %0, %1, %2;"
            : "=r"(peer_h[e]) : "r"(my_h), "r"(pr));
    }

    __syncthreads();
    asm volatile("barrier.cluster.arrive.aligned;" ::: "memory");
    asm volatile("barrier.cluster.wait.aligned;" ::: "memory");

    // first-step gx prefetch
    float gxr[8], gxz[8], gxn[8];
    #pragma unroll
    for (int r = 0; r < 8; r++) {
        const float* g = g_gx + ((size_t)(b0 + r0 + r) * TT) * G3 + gu;
        gxr[r] = g[0]; gxz[r] = g[256]; gxn[r] = g[512];
    }

    for (int t = 0; t < TT; t++) {
        // hprev for own rows
        float hprev[8];
        #pragma unroll
        for (int p = 0; p < 4; p++) {
            float2 v = s_h2[gu * 16 + p0 + p];
            hprev[2 * p] = v.x; hprev[2 * p + 1] = v.y;
        }

        // GEMV from SMEM weights
        float2 aR[4], aZ[4], aN[4];
        #pragma unroll
        for (int p = 0; p < 4; p++) {
            aR[p] = make_float2(0.f, 0.f);
            aZ[p] = make_float2(0.f, 0.f);
            aN[p] = make_float2(0.f, 0.f);
        }
        #pragma unroll 4
        for (int k4 = 0; k4 < 64; k4++) {
            float4 wr = s_w[(k4 * 3 + 0) * 64 + u];
            float4 wz = s_w[(k4 * 3 + 1) * 64 + u];
            float4 wn = s_w[(k4 * 3 + 2) * 64 + u];
            float wra[4] = {wr.x, wr.y, wr.z, wr.w};
            float wza[4] = {wz.x, wz.y, wz.z, wz.w};
            float wna[4] = {wn.x, wn.y, wn.z, wn.w};
            #pragma unroll
            for (int kk = 0; kk < 4; kk++) {
                int k = 4 * k4 + kk;
                float4 hA = *(const float4*)&s_h2[k * 16 + p0];
                float4 hB = *(const float4*)&s_h2[k * 16 + p0 + 2];
                float2 h0 = make_float2(hA.x, hA.y);
                float2 h1 = make_float2(hA.z, hA.w);
                float2 h2 = make_float2(hB.x, hB.y);
                float2 h3 = make_float2(hB.z, hB.w);
                float2 w2;
                w2 = make_float2(wra[kk], wra[kk]);
                fma2(aR[0], w2, h0); fma2(aR[1], w2, h1);
                fma2(aR[2], w2, h2); fma2(aR[3], w2, h3);
                w2 = make_float2(wza[kk], wza[kk]);
                fma2(aZ[0], w2, h0); fma2(aZ[1], w2, h1);
                fma2(aZ[2], w2, h2); fma2(aZ[3], w2, h3);
                w2 = make_float2(wna[kk], wna[kk]);
                fma2(aN[0], w2, h0); fma2(aN[1], w2, h1);
                fma2(aN[2], w2, h2); fma2(aN[3], w2, h3);
            }
        }

        // gates
        float hnew[8];
        #pragma unroll
        for (int p = 0; p < 4; p++) {
            float gr[2] = {aR[p].x, aR[p].y};
            float gz[2] = {aZ[p].x, aZ[p].y};
            float gn[2] = {aN[p].x, aN[p].y};
            #pragma unroll
            for (int e = 0; e < 2; e++) {
                int r = 2 * p + e;
                float rr = siga(gxr[r] + gr[e] + bhr);
                float zz = siga(gxz[r] + gz[e] + bhz);
                float nn = tanha(gxn[r] + rr * (gn[e] + bhn));
                hnew[r] = nn + zz * (hprev[r] - nn);
            }
        }

        if (t == TT - 1) {
            #pragma unroll
            for (int r = 0; r < 8; r++) {
                g_seq[((size_t)(b0 + r0 + r) * TT + t) * HID + gu] = hnew[r];
                h_final[(size_t)(b0 + r0 + r) * HID + gu] = hnew[r];
            }
            break;
        }

        // barrier 1: all cluster reads of s_h2 done. overlap g_seq stores.
        asm volatile("barrier.cluster.arrive.aligned;" ::: "memory");
        #pragma unroll
        for (int r = 0; r < 8; r++)
            g_seq[((size_t)(b0 + r0 + r) * TT + t) * HID + gu] = hnew[r];
        asm volatile("barrier.cluster.wait.aligned;" ::: "memory");

        // write (t+1)-masked h: local slice + 3 peers
        const int bit = (t + 1) & 31;
        #pragma unroll
        for (int p = 0; p < 4; p++) {
            float2 v;
            v.x = ((mw[2 * p]     >> bit) & 1u) ? 0.f : hnew[2 * p];
            v.y = ((mw[2 * p + 1] >> bit) & 1u) ? 0.f : hnew[2 * p + 1];
            s_h2[gu * 16 + p0 + p] = v;
            uint32_t off = (uint32_t)((gu * 16 + p0 + p) * sizeof(float2));
            unsigned long long vv = *(const unsigned long long*)&v;
            asm volatile("st.shared::cluster.b64 [%0], %1;"
                         :: "r"(peer_h[0] + off), "l"(vv) : "memory");
            asm volatile("st.shared::cluster.b64 [%0], %1;"
                         :: "r"(peer_h[1] + off), "l"(vv) : "memory");
            asm volatile("st.shared::cluster.b64 [%0], %1;"
                         :: "r"(peer_h[2] + off), "l"(vv) : "memory");
        }

        // reload mask window when crossing 32-step boundary
        if (((t + 2) & 31) == 0) {
            int w = (t + 2) >> 5;
            if (w < 8) {
                #pragma unroll
                for (int r = 0; r < 8; r++) mw[r] = g_mb[(b0 + r0 + r) * 8 + w];
            }
        }

        // barrier 2: h writes visible. overlap next-step gx prefetch.
        asm volatile("barrier.cluster.arrive.aligned;" ::: "memory");
        #pragma unroll
        for (int r = 0; r < 8; r++) {
            const float* g = g_gx + ((size_t)(b0 + r0 + r) * TT + t + 1) * G3 + gu;
            gxr[r] = g[0]; gxz[r] = g[256]; gxn[r] = g[512];
        }
        asm volatile("barrier.cluster.wait.aligned;" ::: "memory");
    }
}

// ---- post: out = mish(seq) @ W_out + b_out (unchanged) ---------------------
__global__ __launch_bounds__(256) void post_kernel(
    const float* __restrict__ W_out, const float* __restrict__ b_out,
    float* __restrict__ out)
{
    __shared__ float s_m2[HID][32];

    const int tid = threadIdx.x;
    const size_t row0 = (size_t)blockIdx.x * 32;

    {
        const int row = tid & 31;
        const int kc  = (tid >> 5) * 32;
        const float* src = g_seq + (row0 + row) * HID + kc;
        #pragma unroll
        for (int c = 0; c < 8; c++) {
            float4 v = *(const float4*)(src + 4 * c);
            float hv[4] = {v.x, v.y, v.z, v.w};
            #pragma unroll
            for (int e = 0; e < 4; e++) {
                float h = hv[e];
                float sp = __logf(1.f + __expf(h));
                s_m2[kc + 4 * c + e][row] = h * tanha(sp);
            }
        }
    }
    __syncthreads();

    if (tid < 192) {
        const int pg = tid / 24;
        const int l  = tid - pg * 24;
        float2 a0 = make_float2(0.f, 0.f), a1 = make_float2(0.f, 0.f);
        #pragma unroll 4
        for (int k = 0; k < HID; k++) {
            float4 m4 = *(const float4*)&s_m2[k][4 * pg];
            float w = __ldg(W_out + k * LAT + l);
            float2 w2 = make_float2(w, w);
            fma2(a0, w2, make_float2(m4.x, m4.y));
            fma2(a1, w2, make_float2(m4.z, m4.w));
        }
        const float bl = b_out[l];
        out[(row0 + 4 * pg + 0) * LAT + l] = a0.x + bl;
        out[(row0 + 4 * pg + 1) * LAT + l] = a0.y + bl;
        out[(row0 + 4 * pg + 2) * LAT + l] = a1.x + bl;
        out[(row0 + 4 * pg + 3) * LAT + l] = a1.y + bl;
    }
}

// ---------------------------------------------------------------------------
extern "C" void kernel_launch(void* const* d_in, const int* in_sizes, int n_in,
                              void* d_out, int out_size) {
    const float* obs     = (const float*)d_in[0];
    const int*   is_init = (const int*)  d_in[1];
    const float* hx      = (const float*)d_in[2];
    const float* W_in    = (const float*)d_in[3];
    const float* b_in    = (const float*)d_in[4];
    const float* W_ih    = (const float*)d_in[5];
    const float* b_ih    = (const float*)d_in[6];
    const float* W_hh    = (const float*)d_in[7];
    const float* b_hh    = (const float*)d_in[8];
    const float* W_out   = (const float*)d_in[9];
    const float* b_out   = (const float*)d_in[10];

    float* out     = (float*)d_out;                 // [B,T,LAT]
    float* h_final = out + (size_t)BB * TT * LAT;   // [B,HID]

    cudaFuncSetAttribute(rec_kernel,
                         cudaFuncAttributeMaxDynamicSharedMemorySize, REC_SMEM);

    tr_kernel<<<((HID / 4) * G3 + 255) / 256, 256>>>(W_hh);
    mask_kernel<<<BB * 8 / 256, 256>>>(is_init);
    pre_kernel<<<(BB * TT) / 32, 256>>>(obs, W_in, b_in, W_ih, b_ih);
    rec_kernel<<<128, 256, REC_SMEM>>>(hx, b_hh, h_final);
    post_kernel<<<(BB * TT) / 32, 256>>>(W_out, b_out, out);
}

// round 7
// speedup vs baseline: 2.0719x; 1.9174x over previous
#include <cuda_runtime.h>
#include <math.h>
#include <stdint.h>

#define OBS   128
#define PROJ  64
#define HID   256
#define LAT   24
#define BB    1024
#define TT    256
#define G3    768
#define KC4   28                     // k4-blocks cached in SMEM (k = 0..111)
#define WSM_BYTES (KC4 * 3 * 128 * 16)   // 168 KB weight cache

// ---- device scratch --------------------------------------------------------
__device__ float  g_gx [(size_t)BB * TT * G3];   // input-side gates [B*T,768]
__device__ float  g_seq[(size_t)BB * TT * HID];  // h_new per step   [B*T,256]
__device__ float4 g_Wt4[(HID / 4) * G3];         // W_hh repacked [k4][col] float4

// ---- helpers ---------------------------------------------------------------
__device__ __forceinline__ void fma2(float2& d, float2 a, float2 b) {
    unsigned long long& dd = reinterpret_cast<unsigned long long&>(d);
    asm("fma.rn.f32x2 %0, %1, %2, %0;"
        : "+l"(dd)
        : "l"(reinterpret_cast<const unsigned long long&>(a)),
          "l"(reinterpret_cast<const unsigned long long&>(b)));
}
__device__ __forceinline__ float tanha(float x) {
    float y; asm("tanh.approx.f32 %0, %1;" : "=f"(y) : "f"(x)); return y;
}
__device__ __forceinline__ float siga(float x) {       // sigmoid via MUFU.TANH
    return fmaf(0.5f, tanha(0.5f * x), 0.5f);
}

// ---- W_hh repack: g_Wt4[k4*768+col] = {W[4k4][col],...,W[4k4+3][col]} ------
__global__ void tr_kernel(const float* __restrict__ W) {
    int idx = blockIdx.x * 256 + threadIdx.x;
    if (idx >= (HID / 4) * G3) return;
    int k4 = idx / G3, col = idx - k4 * G3;
    float4 v;
    v.x = W[(size_t)(4 * k4 + 0) * G3 + col];
    v.y = W[(size_t)(4 * k4 + 1) * G3 + col];
    v.z = W[(size_t)(4 * k4 + 2) * G3 + col];
    v.w = W[(size_t)(4 * k4 + 3) * G3 + col];
    g_Wt4[idx] = v;
}

// ---- pre: gx = (obs@W_in + b_in)@W_ih + b_ih (unchanged, proven) -----------
__global__ __launch_bounds__(256) void pre_kernel(
    const float* __restrict__ obs, const float* __restrict__ W_in,
    const float* __restrict__ b_in, const float* __restrict__ W_ih,
    const float* __restrict__ b_ih)
{
    __shared__ float s_obsT[OBS][34];
    __shared__ float s_x2[PROJ][34];

    const int tid = threadIdx.x;
    const size_t row0 = (size_t)blockIdx.x * 32;

    for (int i = tid; i < 32 * OBS; i += 256) {
        int r = i >> 7, k = i & 127;
        s_obsT[k][r] = obs[(row0 + r) * OBS + k];
    }
    __syncthreads();

    {
        const int p = tid & 63, rh = tid >> 6;
        const float bi = b_in[p];
        float2 acc[4];
        #pragma unroll
        for (int pr = 0; pr < 4; pr++) acc[pr] = make_float2(bi, bi);
        #pragma unroll 4
        for (int k = 0; k < OBS; k++) {
            float w = W_in[k * PROJ + p];
            float2 w2 = make_float2(w, w);
            #pragma unroll
            for (int pr = 0; pr < 4; pr++)
                fma2(acc[pr], w2, *(const float2*)&s_obsT[k][8 * rh + 2 * pr]);
        }
        #pragma unroll
        for (int pr = 0; pr < 4; pr++) {
            s_x2[p][8 * rh + 2 * pr]     = acc[pr].x;
            s_x2[p][8 * rh + 2 * pr + 1] = acc[pr].y;
        }
    }
    __syncthreads();

    const int j = tid;
    const float bh0 = b_ih[j], bh1 = b_ih[j + 256], bh2 = b_ih[j + 512];
    for (int rt = 0; rt < 2; rt++) {
        float2 a0[8], a1[8], a2[8];
        #pragma unroll
        for (int pr = 0; pr < 8; pr++) {
            a0[pr] = make_float2(bh0, bh0);
            a1[pr] = make_float2(bh1, bh1);
            a2[pr] = make_float2(bh2, bh2);
        }
        #pragma unroll 2
        for (int p = 0; p < PROJ; p++) {
            float w0 = W_ih[p * G3 + j];
            float w1 = W_ih[p * G3 + j + 256];
            float w2 = W_ih[p * G3 + j + 512];
            float2 w02 = make_float2(w0, w0);
            float2 w12 = make_float2(w1, w1);
            float2 w22 = make_float2(w2, w2);
            #pragma unroll
            for (int pr = 0; pr < 8; pr++) {
                float2 xv = *(const float2*)&s_x2[p][16 * rt + 2 * pr];
                fma2(a0[pr], w02, xv);
                fma2(a1[pr], w12, xv);
                fma2(a2[pr], w22, xv);
            }
        }
        #pragma unroll
        for (int pr = 0; pr < 8; pr++) {
            size_t r = row0 + rt * 16 + 2 * pr;
            g_gx[r * G3 + j]             = a0[pr].x;
            g_gx[(r + 1) * G3 + j]       = a0[pr].y;
            g_gx[r * G3 + j + 256]       = a1[pr].x;
            g_gx[(r + 1) * G3 + j + 256] = a1[pr].y;
            g_gx[r * G3 + j + 512]       = a2[pr].x;
            g_gx[(r + 1) * G3 + j + 512] = a2[pr].y;
        }
    }
}

// ---- rec: cluster-2 scan, R3 structure + SMEM weight cache for k<112 -------
// 64 clusters x 2 CTAs, 256 threads. CTA rank q: hidden units q*128..+127.
// Thread: uu = tid&127 (unit), rg = tid>>7 (rows 8rg..8rg+7, pairs 4rg..4rg+3).
// k = 0..111: weights from SMEM cache (s_wc). k = 112..255: streamed from L2
// via double-buffered register pipeline (8-k blocks).

#define LDW8(dst, bb)                                           \
    {                                                           \
        _Pragma("unroll")                                       \
        for (int u = 0; u < 2; u++) {                           \
            size_t kb = (size_t)(2 * (bb) + u) * G3;            \
            dst[3 * u + 0] = g_Wt4[kb + gu];                    \
            dst[3 * u + 1] = g_Wt4[kb + 256 + gu];              \
            dst[3 * u + 2] = g_Wt4[kb + 512 + gu];              \
        }                                                       \
    }

#define GATES_FMA(wr, wz, wn, kbase)                                          \
    {                                                                         \
        float wra[4] = {wr.x, wr.y, wr.z, wr.w};                              \
        float wza[4] = {wz.x, wz.y, wz.z, wz.w};                              \
        float wna[4] = {wn.x, wn.y, wn.z, wn.w};                              \
        _Pragma("unroll")                                                     \
        for (int kk = 0; kk < 4; kk++) {                                      \
            int k = (kbase) + kk;                                             \
            float4 hA = *(const float4*)&s_hp[rb][k][p0];                     \
            float4 hB = *(const float4*)&s_hp[rb][k][p0 + 2];                 \
            float2 h0 = make_float2(hA.x, hA.y);                              \
            float2 h1 = make_float2(hA.z, hA.w);                              \
            float2 h2 = make_float2(hB.x, hB.y);                              \
            float2 h3 = make_float2(hB.z, hB.w);                              \
            float2 w2;                                                        \
            w2 = make_float2(wra[kk], wra[kk]);                               \
            fma2(ar[0], w2, h0); fma2(ar[1], w2, h1);                         \
            fma2(ar[2], w2, h2); fma2(ar[3], w2, h3);                         \
            w2 = make_float2(wza[kk], wza[kk]);                               \
            fma2(az[0], w2, h0); fma2(az[1], w2, h1);                         \
            fma2(az[2], w2, h2); fma2(az[3], w2, h3);                         \
            w2 = make_float2(wna[kk], wna[kk]);                               \
            fma2(an[0], w2, h0); fma2(an[1], w2, h1);                         \
            fma2(an[2], w2, h2); fma2(an[3], w2, h3);                         \
        }                                                                     \
    }

#define COMP8(buf, bb)                                                        \
    {                                                                         \
        _Pragma("unroll")                                                     \
        for (int u = 0; u < 2; u++) {                                         \
            float4 wr = buf[3 * u], wz = buf[3 * u + 1], wn = buf[3 * u + 2]; \
            GATES_FMA(wr, wz, wn, 8 * (bb) + 4 * u);                          \
        }                                                                     \
    }

__global__ __launch_bounds__(256) __cluster_dims__(2, 1, 1)
void rec_kernel(const int* __restrict__ is_init, const float* __restrict__ hx,
                const float* __restrict__ b_hh, float* __restrict__ h_final)
{
    __shared__ float2 s_hp[2][HID][8];          // 32 KB
    __shared__ unsigned char s_rst[16][TT];     //  4 KB
    extern __shared__ float4 s_wc[];            // [ (k4*3+gate)*128 + uu ], 168 KB

    const int tid = threadIdx.x;
    const int q   = blockIdx.x & 1;
    const int b0  = (blockIdx.x >> 1) * 16;
    const int uu  = tid & 127;
    const int rg  = tid >> 7;
    const int gu  = q * 128 + uu;
    const int p0  = rg * 4;
    const int r0  = rg * 8;

    // fill weight cache: k4 = 0..KC4-1, gates packed per k4
    for (int i = tid; i < KC4 * 3 * 128; i += 256) {
        int k4 = i / 384, rem = i - k4 * 384;
        int g = rem >> 7, u2 = rem & 127;
        s_wc[i] = g_Wt4[(size_t)k4 * G3 + g * 256 + q * 128 + u2];
    }
    for (int i = tid; i < 16 * TT; i += 256) {
        int r = i >> 8, t = i & 255;
        s_rst[r][t] = (unsigned char)(is_init[(b0 + r) * TT + t] != 0);
    }
    for (int i = tid; i < HID * 8; i += 256) {
        int k = i >> 3, p = i & 7;
        float h0 = (is_init[(b0 + 2 * p) * TT] != 0)     ? 0.f : hx[(b0 + 2 * p) * HID + k];
        float h1 = (is_init[(b0 + 2 * p + 1) * TT] != 0) ? 0.f : hx[(b0 + 2 * p + 1) * HID + k];
        s_hp[0][k][p] = make_float2(h0, h1);
    }
    __syncthreads();

    const float bhr = b_hh[gu], bhz = b_hh[256 + gu], bhn = b_hh[512 + gu];

    uint32_t my_base;
    asm("{ .reg .u64 t0; cvta.to.shared.u64 t0, %1; cvt.u32.u64 %0, t0; }"
        : "=r"(my_base) : "l"(&s_hp[0][0][0]));
    uint32_t peer_base;
    asm("mapa.shared::cluster.u32 %0, %1, %2;"
        : "=r"(peer_base) : "r"(my_base), "r"(q ^ 1));

    for (int t = 0; t < TT; t++) {
        const int rb = t & 1, wb = rb ^ 1;

        // prefetch input-side gates (consumed after GEMV)
        float gxr[8], gxz[8], gxn[8];
        #pragma unroll
        for (int r = 0; r < 8; r++) {
            const float* g = g_gx + ((size_t)(b0 + r0 + r) * TT + t) * G3;
            gxr[r] = g[gu]; gxz[r] = g[256 + gu]; gxn[r] = g[512 + gu];
        }
        float hprev[8];
        #pragma unroll
        for (int p = 0; p < 4; p++) {
            float2 v = s_hp[rb][gu][p0 + p];
            hprev[2 * p] = v.x; hprev[2 * p + 1] = v.y;
        }

        float2 ar[4], az[4], an[4];
        #pragma unroll
        for (int p = 0; p < 4; p++) {
            ar[p] = make_float2(0.f, 0.f);
            az[p] = make_float2(0.f, 0.f);
            an[p] = make_float2(0.f, 0.f);
        }

        // ---- part 1: k = 0..111 from SMEM weight cache ----
        // prime the streamed part's first two blocks first (hides L2 latency
        // behind the whole SMEM part)
        float4 wA[6], wB[6];
        LDW8(wA, 14);
        LDW8(wB, 15);

        #pragma unroll 4
        for (int k4 = 0; k4 < KC4; k4++) {
            float4 wr = s_wc[(k4 * 3 + 0) * 128 + uu];
            float4 wz = s_wc[(k4 * 3 + 1) * 128 + uu];
            float4 wn = s_wc[(k4 * 3 + 2) * 128 + uu];
            GATES_FMA(wr, wz, wn, 4 * k4);
        }

        // ---- part 2: k = 112..255 streamed, double-buffered ----
        #pragma unroll 1
        for (int bb = 14; bb < 30; bb += 2) {
            COMP8(wA, bb);
            LDW8(wA, bb + 2);
            COMP8(wB, bb + 1);
            LDW8(wB, bb + 3);
        }
        COMP8(wA, 30);
        COMP8(wB, 31);

        // gates (MUFU.TANH)
        float hnew[8];
        #pragma unroll
        for (int p = 0; p < 4; p++) {
            float gr[2] = {ar[p].x, ar[p].y};
            float gz[2] = {az[p].x, az[p].y};
            float gn[2] = {an[p].x, an[p].y};
            #pragma unroll
            for (int e = 0; e < 2; e++) {
                int r = 2 * p + e;
                float rr = siga(gxr[r] + gr[e] + bhr);
                float zz = siga(gxz[r] + gz[e] + bhz);
                float nn = tanha(gxn[r] + rr * (gn[e] + bhn));
                hnew[r] = nn + zz * (hprev[r] - nn);
            }
        }

        if (t == TT - 1) {
            #pragma unroll
            for (int r = 0; r < 8; r++) {
                g_seq[((size_t)(b0 + r0 + r) * TT + t) * HID + gu] = hnew[r];
                h_final[(size_t)(b0 + r0 + r) * HID + gu] = hnew[r];
            }
            break;
        }

        // write (t+1)-masked h pairs locally + to peer; overlap g_seq stores
        // with the cluster barrier.
        #pragma unroll
        for (int p = 0; p < 4; p++) {
            float2 v;
            v.x = s_rst[r0 + 2 * p][t + 1]     ? 0.f : hnew[2 * p];
            v.y = s_rst[r0 + 2 * p + 1][t + 1] ? 0.f : hnew[2 * p + 1];
            s_hp[wb][gu][p0 + p] = v;
            uint32_t off = (uint32_t)(((wb * HID + gu) * 8 + p0 + p) * sizeof(float2));
            asm volatile("st.shared::cluster.b64 [%0], %1;"
                         :: "r"(peer_base + off),
                            "l"(*(const unsigned long long*)&v) : "memory");
        }
        asm volatile("barrier.cluster.arrive.aligned;" ::: "memory");
        #pragma unroll
        for (int r = 0; r < 8; r++)
            g_seq[((size_t)(b0 + r0 + r) * TT + t) * HID + gu] = hnew[r];
        asm volatile("barrier.cluster.wait.aligned;" ::: "memory");
    }
}

// ---- post: out = mish(seq) @ W_out + b_out (unchanged) ---------------------
__global__ __launch_bounds__(256) void post_kernel(
    const float* __restrict__ W_out, const float* __restrict__ b_out,
    float* __restrict__ out)
{
    __shared__ float s_m2[HID][32];

    const int tid = threadIdx.x;
    const size_t row0 = (size_t)blockIdx.x * 32;

    {
        const int row = tid & 31;
        const int kc  = (tid >> 5) * 32;
        const float* src = g_seq + (row0 + row) * HID + kc;
        #pragma unroll
        for (int c = 0; c < 8; c++) {
            float4 v = *(const float4*)(src + 4 * c);
            float hv[4] = {v.x, v.y, v.z, v.w};
            #pragma unroll
            for (int e = 0; e < 4; e++) {
                float h = hv[e];
                float sp = __logf(1.f + __expf(h));
                s_m2[kc + 4 * c + e][row] = h * tanha(sp);
            }
        }
    }
    __syncthreads();

    if (tid < 192) {
        const int pg = tid / 24;
        const int l  = tid - pg * 24;
        float2 a0 = make_float2(0.f, 0.f), a1 = make_float2(0.f, 0.f);
        #pragma unroll 4
        for (int k = 0; k < HID; k++) {
            float4 m4 = *(const float4*)&s_m2[k][4 * pg];
            float w = __ldg(W_out + k * LAT + l);
            float2 w2 = make_float2(w, w);
            fma2(a0, w2, make_float2(m4.x, m4.y));
            fma2(a1, w2, make_float2(m4.z, m4.w));
        }
        const float bl = b_out[l];
        out[(row0 + 4 * pg + 0) * LAT + l] = a0.x + bl;
        out[(row0 + 4 * pg + 1) * LAT + l] = a0.y + bl;
        out[(row0 + 4 * pg + 2) * LAT + l] = a1.x + bl;
        out[(row0 + 4 * pg + 3) * LAT + l] = a1.y + bl;
    }
}

// ---------------------------------------------------------------------------
extern "C" void kernel_launch(void* const* d_in, const int* in_sizes, int n_in,
                              void* d_out, int out_size) {
    const float* obs     = (const float*)d_in[0];
    const int*   is_init = (const int*)  d_in[1];
    const float* hx      = (const float*)d_in[2];
    const float* W_in    = (const float*)d_in[3];
    const float* b_in    = (const float*)d_in[4];
    const float* W_ih    = (const float*)d_in[5];
    const float* b_ih    = (const float*)d_in[6];
    const float* W_hh    = (const float*)d_in[7];
    const float* b_hh    = (const float*)d_in[8];
    const float* W_out   = (const float*)d_in[9];
    const float* b_out   = (const float*)d_in[10];

    float* out     = (float*)d_out;                 // [B,T,LAT]
    float* h_final = out + (size_t)BB * TT * LAT;   // [B,HID]

    cudaFuncSetAttribute(rec_kernel,
                         cudaFuncAttributeMaxDynamicSharedMemorySize, WSM_BYTES);

    tr_kernel<<<((HID / 4) * G3 + 255) / 256, 256>>>(W_hh);
    pre_kernel<<<(BB * TT) / 32, 256>>>(obs, W_in, b_in, W_ih, b_ih);
    rec_kernel<<<BB / 8, 256, WSM_BYTES>>>(is_init, hx, b_hh, h_final);
    post_kernel<<<(BB * TT) / 32, 256>>>(W_out, b_out, out);
}